// round 4
// baseline (speedup 1.0000x reference)
#include <cuda_runtime.h>
#include <cuda_bf16.h>

#define N_NODES 100000
#define N_EDGES 1600000
#define IN_DIM 64
#define HID_DIM 128
#define EMB_DIM 64

// ---- scratch (device globals; no allocation allowed) ----
__device__ float g_dinv[N_NODES];                 // deg -> dinv in place
__device__ float g_xw [N_NODES * HID_DIM];        // xw * dinv[row]  (layer1 source)
__device__ float g_h  [N_NODES * HID_DIM];        // layer1 accumulator
__device__ float g_y  [N_NODES * EMB_DIM];        // yw * dinv[row]  (layer2 source)
__device__ float g_acc2[N_NODES * EMB_DIM];       // layer2 accumulator

// ---------------- degree / norm ----------------
__global__ void k_deg_init() {
    int i = blockIdx.x * blockDim.x + threadIdx.x;
    if (i < N_NODES) g_dinv[i] = 1.0f;            // self loop
}

__global__ void k_deg_count(const int* __restrict__ ei) {
    int e = blockIdx.x * blockDim.x + threadIdx.x;
    if (e < N_EDGES) {
        unsigned c = (unsigned)ei[N_EDGES + e];
        if (c < N_NODES) atomicAdd(&g_dinv[c], 1.0f);
    }
}

__global__ void k_dinv() {
    int i = blockIdx.x * blockDim.x + threadIdx.x;
    if (i < N_NODES) g_dinv[i] = rsqrtf(g_dinv[i]);
}

// ---------------- GEMM1: xw = (x @ W1) * dinv[row] ----------------
// block = 256 threads = 8 warps; each warp does 4 rows, lane covers 4 cols.
__global__ __launch_bounds__(256) void k_gemm1(const float* __restrict__ x,
                                               const float* __restrict__ W1) {
    __shared__ float Ws[IN_DIM * HID_DIM];   // 32 KB
    __shared__ float xs[32 * IN_DIM];        // 8 KB
    int tid = threadIdx.x;
    int row0 = blockIdx.x * 32;

    #pragma unroll
    for (int i = tid * 4; i < IN_DIM * HID_DIM; i += 256 * 4)
        *(float4*)&Ws[i] = *(const float4*)&W1[i];
    #pragma unroll
    for (int i = tid * 4; i < 32 * IN_DIM; i += 256 * 4)
        *(float4*)&xs[i] = *(const float4*)&x[row0 * IN_DIM + i];
    __syncthreads();

    int warp = tid >> 5, lane = tid & 31;
    int rbase = warp * 4;
    float4 a0 = {0,0,0,0}, a1 = {0,0,0,0}, a2 = {0,0,0,0}, a3 = {0,0,0,0};

    #pragma unroll
    for (int k = 0; k < IN_DIM; k++) {
        float4 wv = *(float4*)&Ws[k * HID_DIM + lane * 4];
        float x0 = xs[(rbase + 0) * IN_DIM + k];
        float x1 = xs[(rbase + 1) * IN_DIM + k];
        float x2 = xs[(rbase + 2) * IN_DIM + k];
        float x3 = xs[(rbase + 3) * IN_DIM + k];
        a0.x += x0 * wv.x; a0.y += x0 * wv.y; a0.z += x0 * wv.z; a0.w += x0 * wv.w;
        a1.x += x1 * wv.x; a1.y += x1 * wv.y; a1.z += x1 * wv.z; a1.w += x1 * wv.w;
        a2.x += x2 * wv.x; a2.y += x2 * wv.y; a2.z += x2 * wv.z; a2.w += x2 * wv.w;
        a3.x += x3 * wv.x; a3.y += x3 * wv.y; a3.z += x3 * wv.z; a3.w += x3 * wv.w;
    }

    float4 accs[4] = {a0, a1, a2, a3};
    #pragma unroll
    for (int r = 0; r < 4; r++) {
        int row = row0 + rbase + r;
        float s = g_dinv[row];
        float4 v = accs[r];
        v.x *= s; v.y *= s; v.z *= s; v.w *= s;
        *(float4*)&g_xw[row * HID_DIM + lane * 4] = v;
        *(float4*)&g_h [row * HID_DIM + lane * 4] = v;  // accumulator init = self term
    }
}

// ---------------- scatter layer 1: one warp per edge, 128 floats ----------------
__global__ __launch_bounds__(256) void k_scatter1(const int* __restrict__ ei) {
    int t = blockIdx.x * blockDim.x + threadIdx.x;
    int e = t >> 5;
    if (e >= N_EDGES) return;
    int lane = t & 31;
    unsigned r = (unsigned)ei[e];
    unsigned c = (unsigned)ei[N_EDGES + e];
    if (r >= N_NODES || c >= N_NODES) return;
    float4 v = *(const float4*)&g_xw[(size_t)r * HID_DIM + lane * 4];
    float* dst = &g_h[(size_t)c * HID_DIM + lane * 4];
    asm volatile("red.global.add.v4.f32 [%0], {%1, %2, %3, %4};"
                 :: "l"(dst), "f"(v.x), "f"(v.y), "f"(v.z), "f"(v.w) : "memory");
}

// ---------------- GEMM2: y = (relu(acc1*dinv + b1) @ W2) * dinv[row] ----------------
__global__ __launch_bounds__(256) void k_gemm2(const float* __restrict__ W2,
                                               const float* __restrict__ b1) {
    __shared__ float Ws[HID_DIM * EMB_DIM];  // 32 KB
    __shared__ float hs[32 * HID_DIM];       // 16 KB
    int tid = threadIdx.x;
    int row0 = blockIdx.x * 32;

    #pragma unroll
    for (int i = tid * 4; i < HID_DIM * EMB_DIM; i += 256 * 4)
        *(float4*)&Ws[i] = *(const float4*)&W2[i];

    // load + fuse bias/relu/dinv scaling of hidden activations
    #pragma unroll
    for (int i = tid; i < 32 * HID_DIM / 4; i += 256) {
        int idx4 = i * 4;
        int row_local = idx4 >> 7;          // /128
        int k = idx4 & 127;
        int row = row0 + row_local;
        float s = g_dinv[row];
        float4 hv = *(float4*)&g_h[row * HID_DIM + k];
        float4 bv = *(const float4*)&b1[k];
        float4 o;
        o.x = fmaxf(hv.x * s + bv.x, 0.0f);
        o.y = fmaxf(hv.y * s + bv.y, 0.0f);
        o.z = fmaxf(hv.z * s + bv.z, 0.0f);
        o.w = fmaxf(hv.w * s + bv.w, 0.0f);
        *(float4*)&hs[idx4] = o;
    }
    __syncthreads();

    int warp = tid >> 5, lane = tid & 31;
    int rbase = warp * 4;
    float2 a0 = {0,0}, a1 = {0,0}, a2 = {0,0}, a3 = {0,0};

    #pragma unroll
    for (int k = 0; k < HID_DIM; k++) {
        float2 wv = *(float2*)&Ws[k * EMB_DIM + lane * 2];
        float x0 = hs[(rbase + 0) * HID_DIM + k];
        float x1 = hs[(rbase + 1) * HID_DIM + k];
        float x2 = hs[(rbase + 2) * HID_DIM + k];
        float x3 = hs[(rbase + 3) * HID_DIM + k];
        a0.x += x0 * wv.x; a0.y += x0 * wv.y;
        a1.x += x1 * wv.x; a1.y += x1 * wv.y;
        a2.x += x2 * wv.x; a2.y += x2 * wv.y;
        a3.x += x3 * wv.x; a3.y += x3 * wv.y;
    }

    float2 accs[4] = {a0, a1, a2, a3};
    #pragma unroll
    for (int r = 0; r < 4; r++) {
        int row = row0 + rbase + r;
        float s = g_dinv[row];
        float2 v = accs[r];
        v.x *= s; v.y *= s;
        *(float2*)&g_y   [row * EMB_DIM + lane * 2] = v;
        *(float2*)&g_acc2[row * EMB_DIM + lane * 2] = v;  // self term
    }
}

// ---------------- scatter layer 2: half-warp per edge, 64 floats ----------------
__global__ __launch_bounds__(256) void k_scatter2(const int* __restrict__ ei) {
    int t = blockIdx.x * blockDim.x + threadIdx.x;
    int e = t >> 4;
    if (e >= N_EDGES) return;
    int lane = t & 15;
    unsigned r = (unsigned)ei[e];
    unsigned c = (unsigned)ei[N_EDGES + e];
    if (r >= N_NODES || c >= N_NODES) return;
    float4 v = *(const float4*)&g_y[(size_t)r * EMB_DIM + lane * 4];
    float* dst = &g_acc2[(size_t)c * EMB_DIM + lane * 4];
    asm volatile("red.global.add.v4.f32 [%0], {%1, %2, %3, %4};"
                 :: "l"(dst), "f"(v.x), "f"(v.y), "f"(v.z), "f"(v.w) : "memory");
}

// ---------------- finalize: out = acc2 * dinv[node] + b2 ----------------
__global__ void k_final(const float* __restrict__ b2, float* __restrict__ out) {
    int i = blockIdx.x * blockDim.x + threadIdx.x;
    if (i >= N_NODES * EMB_DIM) return;
    int node = i >> 6;     // /64
    int j = i & 63;
    out[i] = g_acc2[i] * g_dinv[node] + b2[j];
}

extern "C" void kernel_launch(void* const* d_in, const int* in_sizes, int n_in,
                              void* d_out, int out_size) {
    const float* x  = (const float*)d_in[0];
    const int*   ei = (const int*)d_in[1];
    const float* W1 = (const float*)d_in[2];
    const float* b1 = (const float*)d_in[3];
    const float* W2 = (const float*)d_in[4];
    const float* b2 = (const float*)d_in[5];
    float* out = (float*)d_out;

    k_deg_init<<<(N_NODES + 255) / 256, 256>>>();
    k_deg_count<<<(N_EDGES + 255) / 256, 256>>>(ei);
    k_dinv<<<(N_NODES + 255) / 256, 256>>>();

    k_gemm1<<<N_NODES / 32, 256>>>(x, W1);
    k_scatter1<<<(N_EDGES * 32) / 256, 256>>>(ei);

    k_gemm2<<<N_NODES / 32, 256>>>(W2, b1);
    k_scatter2<<<(N_EDGES * 16) / 256, 256>>>(ei);

    k_final<<<(N_NODES * EMB_DIM + 255) / 256, 256>>>(b2, out);
}

// round 5
// speedup vs baseline: 1.9981x; 1.9981x over previous
#include <cuda_runtime.h>
#include <cuda_bf16.h>

#define N_NODES 100000
#define N_EDGES 1600000
#define IN_DIM 64
#define HID_DIM 128
#define EMB_DIM 64
#define SCAN_B 1024
#define NBLK 98            // ceil(100000/1024)

// ---- scratch (device globals; no allocation allowed) ----
__device__ int   g_deg[N_NODES];
__device__ int   g_scan[N_NODES];
__device__ int   g_bsum[NBLK];
__device__ int   g_boff[128];
__device__ int   g_rowptr[N_NODES + 1];
__device__ int   g_cursor[N_NODES];
__device__ int   g_src[N_EDGES];
__device__ float g_dinv[N_NODES];
__device__ float g_xs  [N_NODES * IN_DIM];    // x * dinv[row]
__device__ float g_agg1[N_NODES * IN_DIM];    // aggregated input
__device__ float g_h   [N_NODES * HID_DIM];   // hidden (post relu)
__device__ float g_y   [N_NODES * EMB_DIM];   // (h @ W2) * dinv[row]

// ---------------- CSR build ----------------
__global__ void k_zero_deg() {
    int i = blockIdx.x * blockDim.x + threadIdx.x;
    if (i < N_NODES) g_deg[i] = 0;
}

__global__ void k_hist(const int* __restrict__ ei) {
    int e = blockIdx.x * blockDim.x + threadIdx.x;
    if (e < N_EDGES) {
        unsigned r = (unsigned)ei[e];
        unsigned c = (unsigned)ei[N_EDGES + e];
        if (r < N_NODES && c < N_NODES) atomicAdd(&g_deg[c], 1);
    }
}

__global__ __launch_bounds__(SCAN_B) void k_scan_local() {
    __shared__ int s[SCAN_B];
    int tid = threadIdx.x;
    int i = blockIdx.x * SCAN_B + tid;
    int v = (i < N_NODES) ? g_deg[i] : 0;
    s[tid] = v;
    __syncthreads();
    #pragma unroll
    for (int off = 1; off < SCAN_B; off <<= 1) {
        int t = (tid >= off) ? s[tid - off] : 0;
        __syncthreads();
        s[tid] += t;
        __syncthreads();
    }
    if (i < N_NODES) g_scan[i] = s[tid];
    if (tid == SCAN_B - 1) g_bsum[blockIdx.x] = s[tid];
}

__global__ void k_scan_bsum() {
    __shared__ int s[128];
    int tid = threadIdx.x;
    int v = (tid < NBLK) ? g_bsum[tid] : 0;
    s[tid] = v;
    __syncthreads();
    #pragma unroll
    for (int off = 1; off < 128; off <<= 1) {
        int t = (tid >= off) ? s[tid - off] : 0;
        __syncthreads();
        s[tid] += t;
        __syncthreads();
    }
    g_boff[tid] = s[tid] - v;   // exclusive
}

__global__ void k_scan_final() {
    int i = blockIdx.x * blockDim.x + threadIdx.x;
    if (i >= N_NODES) return;
    int deg = g_deg[i];
    int incl = g_scan[i] + g_boff[i >> 10];
    int excl = incl - deg;
    g_rowptr[i] = excl;
    g_cursor[i] = excl;
    g_dinv[i] = rsqrtf((float)deg + 1.0f);
    if (i == N_NODES - 1) g_rowptr[N_NODES] = incl;
}

__global__ void k_fill(const int* __restrict__ ei) {
    int e = blockIdx.x * blockDim.x + threadIdx.x;
    if (e >= N_EDGES) return;
    unsigned r = (unsigned)ei[e];
    unsigned c = (unsigned)ei[N_EDGES + e];
    if (r < N_NODES && c < N_NODES) {
        int pos = atomicAdd(&g_cursor[c], 1);
        g_src[pos] = (int)r;
    }
}

// ---------------- xs = x * dinv[row] ----------------
__global__ void k_xs(const float* __restrict__ x) {
    int i = blockIdx.x * blockDim.x + threadIdx.x;   // float4 index
    if (i >= N_NODES * (IN_DIM / 4)) return;
    int node = i >> 4;
    float s = g_dinv[node];
    float4 v = *(const float4*)&x[i * 4];
    v.x *= s; v.y *= s; v.z *= s; v.w *= s;
    *(float4*)&g_xs[i * 4] = v;
}

// ---------------- gather (64-dim): agg[c] = src_vec[c] + sum_{r in N(c)} src_vec[r]
// one warp per node; two 16-lane halves each take alternate neighbors (MLP=2).
__global__ __launch_bounds__(256) void k_gather1() {
    int warp = threadIdx.x >> 5;
    int lane = threadIdx.x & 31;
    int node = blockIdx.x * 8 + warp;
    if (node >= N_NODES) return;
    int l = lane & 15, which = lane >> 4;
    const float4* xs4 = (const float4*)g_xs;

    float4 acc;
    if (which == 0) acc = xs4[node * 16 + l];           // self term
    else            acc = make_float4(0.f, 0.f, 0.f, 0.f);

    int beg = g_rowptr[node], end = g_rowptr[node + 1];
    for (int i = beg + which; i < end; i += 2) {
        float4 v = xs4[(size_t)g_src[i] * 16 + l];
        acc.x += v.x; acc.y += v.y; acc.z += v.z; acc.w += v.w;
    }
    acc.x += __shfl_xor_sync(0xffffffffu, acc.x, 16);
    acc.y += __shfl_xor_sync(0xffffffffu, acc.y, 16);
    acc.z += __shfl_xor_sync(0xffffffffu, acc.z, 16);
    acc.w += __shfl_xor_sync(0xffffffffu, acc.w, 16);
    if (which == 0)
        *(float4*)&g_agg1[node * IN_DIM + l * 4] = acc;
}

// ---------------- GEMM1: h = relu(dinv[c] * agg1 @ W1 + b1) ----------------
__global__ __launch_bounds__(256) void k_gemm1(const float* __restrict__ W1,
                                               const float* __restrict__ b1) {
    __shared__ float Ws[IN_DIM * HID_DIM];   // 32 KB
    __shared__ float xs[32 * IN_DIM];        // 8 KB
    int tid = threadIdx.x;
    int row0 = blockIdx.x * 32;

    #pragma unroll
    for (int i = tid * 4; i < IN_DIM * HID_DIM; i += 256 * 4)
        *(float4*)&Ws[i] = *(const float4*)&W1[i];
    // load agg1 tile with dinv[row] scaling fused
    #pragma unroll
    for (int i = tid; i < 32 * IN_DIM / 4; i += 256) {
        int idx4 = i * 4;
        int row = row0 + (idx4 >> 6);
        float s = g_dinv[row];
        float4 v = *(float4*)&g_agg1[row0 * IN_DIM + idx4];
        v.x *= s; v.y *= s; v.z *= s; v.w *= s;
        *(float4*)&xs[idx4] = v;
    }
    __syncthreads();

    int warp = tid >> 5, lane = tid & 31;
    int rbase = warp * 4;
    float4 a0 = {0,0,0,0}, a1 = {0,0,0,0}, a2 = {0,0,0,0}, a3 = {0,0,0,0};

    #pragma unroll
    for (int k = 0; k < IN_DIM; k++) {
        float4 wv = *(float4*)&Ws[k * HID_DIM + lane * 4];
        float x0 = xs[(rbase + 0) * IN_DIM + k];
        float x1 = xs[(rbase + 1) * IN_DIM + k];
        float x2 = xs[(rbase + 2) * IN_DIM + k];
        float x3 = xs[(rbase + 3) * IN_DIM + k];
        a0.x += x0 * wv.x; a0.y += x0 * wv.y; a0.z += x0 * wv.z; a0.w += x0 * wv.w;
        a1.x += x1 * wv.x; a1.y += x1 * wv.y; a1.z += x1 * wv.z; a1.w += x1 * wv.w;
        a2.x += x2 * wv.x; a2.y += x2 * wv.y; a2.z += x2 * wv.z; a2.w += x2 * wv.w;
        a3.x += x3 * wv.x; a3.y += x3 * wv.y; a3.z += x3 * wv.z; a3.w += x3 * wv.w;
    }

    float4 bv = *(const float4*)&b1[lane * 4];
    float4 accs[4] = {a0, a1, a2, a3};
    #pragma unroll
    for (int r = 0; r < 4; r++) {
        int row = row0 + rbase + r;
        float4 v = accs[r];
        v.x = fmaxf(v.x + bv.x, 0.0f);
        v.y = fmaxf(v.y + bv.y, 0.0f);
        v.z = fmaxf(v.z + bv.z, 0.0f);
        v.w = fmaxf(v.w + bv.w, 0.0f);
        *(float4*)&g_h[row * HID_DIM + lane * 4] = v;
    }
}

// ---------------- GEMM2: y = (h @ W2) * dinv[row] ----------------
__global__ __launch_bounds__(256) void k_gemm2(const float* __restrict__ W2) {
    __shared__ float Ws[HID_DIM * EMB_DIM];  // 32 KB
    __shared__ float hs[32 * HID_DIM];       // 16 KB
    int tid = threadIdx.x;
    int row0 = blockIdx.x * 32;

    #pragma unroll
    for (int i = tid * 4; i < HID_DIM * EMB_DIM; i += 256 * 4)
        *(float4*)&Ws[i] = *(const float4*)&W2[i];
    #pragma unroll
    for (int i = tid * 4; i < 32 * HID_DIM; i += 256 * 4)
        *(float4*)&hs[i] = *(float4*)&g_h[row0 * HID_DIM + i];
    __syncthreads();

    int warp = tid >> 5, lane = tid & 31;
    int rbase = warp * 4;
    float2 a0 = {0,0}, a1 = {0,0}, a2 = {0,0}, a3 = {0,0};

    #pragma unroll
    for (int k = 0; k < HID_DIM; k++) {
        float2 wv = *(float2*)&Ws[k * EMB_DIM + lane * 2];
        float x0 = hs[(rbase + 0) * HID_DIM + k];
        float x1 = hs[(rbase + 1) * HID_DIM + k];
        float x2 = hs[(rbase + 2) * HID_DIM + k];
        float x3 = hs[(rbase + 3) * HID_DIM + k];
        a0.x += x0 * wv.x; a0.y += x0 * wv.y;
        a1.x += x1 * wv.x; a1.y += x1 * wv.y;
        a2.x += x2 * wv.x; a2.y += x2 * wv.y;
        a3.x += x3 * wv.x; a3.y += x3 * wv.y;
    }

    float2 accs[4] = {a0, a1, a2, a3};
    #pragma unroll
    for (int r = 0; r < 4; r++) {
        int row = row0 + rbase + r;
        float s = g_dinv[row];
        float2 v = accs[r];
        v.x *= s; v.y *= s;
        *(float2*)&g_y[row * EMB_DIM + lane * 2] = v;
    }
}

// ---------------- gather 2 + finalize: out = dinv[c]*(y[c] + sum y[r]) + b2 ----------------
__global__ __launch_bounds__(256) void k_gather2(const float* __restrict__ b2,
                                                 float* __restrict__ out) {
    int warp = threadIdx.x >> 5;
    int lane = threadIdx.x & 31;
    int node = blockIdx.x * 8 + warp;
    if (node >= N_NODES) return;
    int l = lane & 15, which = lane >> 4;
    const float4* y4 = (const float4*)g_y;

    float4 acc;
    if (which == 0) acc = y4[node * 16 + l];            // self term
    else            acc = make_float4(0.f, 0.f, 0.f, 0.f);

    int beg = g_rowptr[node], end = g_rowptr[node + 1];
    for (int i = beg + which; i < end; i += 2) {
        float4 v = y4[(size_t)g_src[i] * 16 + l];
        acc.x += v.x; acc.y += v.y; acc.z += v.z; acc.w += v.w;
    }
    acc.x += __shfl_xor_sync(0xffffffffu, acc.x, 16);
    acc.y += __shfl_xor_sync(0xffffffffu, acc.y, 16);
    acc.z += __shfl_xor_sync(0xffffffffu, acc.z, 16);
    acc.w += __shfl_xor_sync(0xffffffffu, acc.w, 16);

    if (which == 0) {
        float s = g_dinv[node];
        float4 bv = *(const float4*)&b2[l * 4];
        acc.x = acc.x * s + bv.x;
        acc.y = acc.y * s + bv.y;
        acc.z = acc.z * s + bv.z;
        acc.w = acc.w * s + bv.w;
        *(float4*)&out[node * EMB_DIM + l * 4] = acc;
    }
}

extern "C" void kernel_launch(void* const* d_in, const int* in_sizes, int n_in,
                              void* d_out, int out_size) {
    const float* x  = (const float*)d_in[0];
    const int*   ei = (const int*)d_in[1];
    const float* W1 = (const float*)d_in[2];
    const float* b1 = (const float*)d_in[3];
    const float* W2 = (const float*)d_in[4];
    const float* b2 = (const float*)d_in[5];
    float* out = (float*)d_out;

    // CSR build
    k_zero_deg<<<(N_NODES + 255) / 256, 256>>>();
    k_hist<<<(N_EDGES + 255) / 256, 256>>>(ei);
    k_scan_local<<<NBLK, SCAN_B>>>();
    k_scan_bsum<<<1, 128>>>();
    k_scan_final<<<(N_NODES + 255) / 256, 256>>>();
    k_fill<<<(N_EDGES + 255) / 256, 256>>>(ei);

    // layer 1: aggregate input (64-dim), then GEMM
    k_xs<<<(N_NODES * (IN_DIM / 4) + 255) / 256, 256>>>(x);
    k_gather1<<<(N_NODES + 7) / 8, 256>>>();
    k_gemm1<<<N_NODES / 32, 256>>>(W1, b1);

    // layer 2: GEMM first (128->64), then aggregate (64-dim) + finalize
    k_gemm2<<<N_NODES / 32, 256>>>(W2);
    k_gather2<<<(N_NODES + 7) / 8, 256>>>(b2, out);
}

// round 6
// speedup vs baseline: 2.9226x; 1.4627x over previous
#include <cuda_runtime.h>
#include <cuda_fp16.h>
#include <cuda_bf16.h>
#include <cstdint>

#define N_NODES 100000
#define N_EDGES 1600000
#define IN_DIM 64
#define HID_DIM 128
#define EMB_DIM 64
#define SCAN_B 1024
#define NBLK 98            // ceil(100000/1024)

// ---- scratch (device globals; no allocation allowed) ----
__device__ int   g_deg[N_NODES];
__device__ int   g_scan[N_NODES];
__device__ int   g_bsum[NBLK];
__device__ int   g_rowptr[N_NODES + 1];
__device__ int   g_cursor[N_NODES];
__device__ int   g_src[N_EDGES];
__device__ float g_dinv[N_NODES];
__device__ __align__(16) __half g_xsh [N_NODES * IN_DIM];   // x * dinv[row] (fp16)
__device__ __align__(16) __half g_aggh[N_NODES * IN_DIM];   // dinv[c] * aggregated input (fp16)
__device__ __align__(16) __half g_h   [N_NODES * HID_DIM];  // hidden post-relu (fp16)
__device__ __align__(16) __half g_yh  [N_NODES * EMB_DIM];  // (h @ W2) * dinv[row] (fp16)

union PK2 { __half2 h[2]; uint2 u; };

// ---------------- CSR build ----------------
__global__ void k_zero_deg() {
    int i = blockIdx.x * blockDim.x + threadIdx.x;
    if (i < N_NODES) g_deg[i] = 0;
}

__global__ void k_hist(const int* __restrict__ ei) {
    int e = blockIdx.x * blockDim.x + threadIdx.x;
    if (e < N_EDGES) {
        unsigned c = (unsigned)ei[N_EDGES + e];
        if (c < N_NODES) atomicAdd(&g_deg[c], 1);
    }
}

__global__ __launch_bounds__(SCAN_B) void k_scan_local() {
    __shared__ int s[SCAN_B];
    int tid = threadIdx.x;
    int i = blockIdx.x * SCAN_B + tid;
    int v = (i < N_NODES) ? g_deg[i] : 0;
    s[tid] = v;
    __syncthreads();
    #pragma unroll
    for (int off = 1; off < SCAN_B; off <<= 1) {
        int t = (tid >= off) ? s[tid - off] : 0;
        __syncthreads();
        s[tid] += t;
        __syncthreads();
    }
    if (i < N_NODES) g_scan[i] = s[tid];
    if (tid == SCAN_B - 1) g_bsum[blockIdx.x] = s[tid];
}

// fused: per-block redundant scan of the 98 block sums, then finalize rowptr/dinv
__global__ __launch_bounds__(256) void k_scan_final() {
    __shared__ int s[128];
    int tid = threadIdx.x;
    if (tid < 128) s[tid] = (tid < NBLK) ? g_bsum[tid] : 0;
    __syncthreads();
    #pragma unroll
    for (int off = 1; off < 128; off <<= 1) {
        int t = 0;
        if (tid < 128 && tid >= off) t = s[tid - off];
        __syncthreads();
        if (tid < 128) s[tid] += t;
        __syncthreads();
    }
    int i = blockIdx.x * 256 + tid;
    if (i >= N_NODES) return;
    int blk = i >> 10;
    int boff = (blk == 0) ? 0 : s[blk - 1];
    int deg = g_deg[i];
    int incl = g_scan[i] + boff;
    int excl = incl - deg;
    g_rowptr[i] = excl;
    g_cursor[i] = excl;
    g_dinv[i] = rsqrtf((float)deg + 1.0f);
    if (i == N_NODES - 1) g_rowptr[N_NODES] = incl;
}

__global__ void k_fill(const int* __restrict__ ei) {
    int e = blockIdx.x * blockDim.x + threadIdx.x;
    if (e >= N_EDGES) return;
    unsigned r = (unsigned)ei[e];
    unsigned c = (unsigned)ei[N_EDGES + e];
    if (r < N_NODES && c < N_NODES) {
        int pos = atomicAdd(&g_cursor[c], 1);
        g_src[pos] = (int)r;
    }
}

// ---------------- xs = x * dinv[row]  (fp32 -> fp16) ----------------
__global__ void k_xs(const float* __restrict__ x) {
    int i = blockIdx.x * blockDim.x + threadIdx.x;   // float4 index
    if (i >= N_NODES * (IN_DIM / 4)) return;
    int node = i >> 4;
    float s = g_dinv[node];
    float4 v = *(const float4*)&x[i * 4];
    PK2 p;
    p.h[0] = __floats2half2_rn(v.x * s, v.y * s);
    p.h[1] = __floats2half2_rn(v.z * s, v.w * s);
    *(uint2*)&g_xsh[i * 4] = p.u;
}

// ---------------- gather1 (64-dim fp16): aggh[c] = dinv[c]*(xs[c] + sum xs[r]) ----------------
__global__ __launch_bounds__(256) void k_gather1() {
    int warp = threadIdx.x >> 5;
    int lane = threadIdx.x & 31;
    int node = blockIdx.x * 8 + warp;
    if (node >= N_NODES) return;
    int l = lane & 15, which = lane >> 4;

    float4 acc = make_float4(0.f, 0.f, 0.f, 0.f);
    if (which == 0) {
        uint2 u = *(const uint2*)&g_xsh[(size_t)node * IN_DIM + l * 4];
        float2 f0 = __half22float2(*(__half2*)&u.x);
        float2 f1 = __half22float2(*(__half2*)&u.y);
        acc = make_float4(f0.x, f0.y, f1.x, f1.y);
    }
    int beg = g_rowptr[node], end = g_rowptr[node + 1];
    for (int i = beg + which; i < end; i += 2) {
        uint2 u = *(const uint2*)&g_xsh[(size_t)g_src[i] * IN_DIM + l * 4];
        float2 f0 = __half22float2(*(__half2*)&u.x);
        float2 f1 = __half22float2(*(__half2*)&u.y);
        acc.x += f0.x; acc.y += f0.y; acc.z += f1.x; acc.w += f1.y;
    }
    acc.x += __shfl_xor_sync(0xffffffffu, acc.x, 16);
    acc.y += __shfl_xor_sync(0xffffffffu, acc.y, 16);
    acc.z += __shfl_xor_sync(0xffffffffu, acc.z, 16);
    acc.w += __shfl_xor_sync(0xffffffffu, acc.w, 16);
    if (which == 0) {
        float s = g_dinv[node];
        PK2 p;
        p.h[0] = __floats2half2_rn(acc.x * s, acc.y * s);
        p.h[1] = __floats2half2_rn(acc.z * s, acc.w * s);
        *(uint2*)&g_aggh[(size_t)node * IN_DIM + l * 4] = p.u;
    }
}

// ---------------- GEMM1 (HMMA): h = relu(aggh @ W1 + b1), fp16 out ----------------
// block: 32 rows x 128 cols, 8 warps (2x4), warp tile 16x32, K=64 (4 k-steps)
__global__ __launch_bounds__(256) void k_gemm1(const float* __restrict__ W1,
                                               const float* __restrict__ b1) {
    __shared__ __half As[32 * 72];     // LDA=72 halves (144B rows, 4-bank rotation)
    __shared__ __half Bs[64 * 136];    // LDB=136 halves (272B rows)
    int tid = threadIdx.x;
    int row0 = blockIdx.x * 32;

    {   // A: 32x64 halves, each thread one 16B chunk
        int row = tid >> 3, c8 = (tid & 7) * 8;
        uint4 v = *(const uint4*)&g_aggh[(size_t)(row0 + row) * IN_DIM + c8];
        *(uint4*)&As[row * 72 + c8] = v;
    }
    // B: W1 fp32 64x128 -> fp16 shared
    #pragma unroll
    for (int i = tid; i < 64 * 128 / 4; i += 256) {
        int idx4 = i * 4;
        int k = idx4 >> 7, n = idx4 & 127;
        float4 w = *(const float4*)&W1[idx4];
        PK2 p;
        p.h[0] = __floats2half2_rn(w.x, w.y);
        p.h[1] = __floats2half2_rn(w.z, w.w);
        *(uint2*)&Bs[k * 136 + n] = p.u;
    }
    __syncthreads();

    int warp = tid >> 5, lane = tid & 31;
    int wm = warp >> 2, wn = warp & 3;
    float d[4][4] = {};

    #pragma unroll
    for (int ks = 0; ks < 4; ks++) {
        int k0 = ks * 16;
        uint32_t a0, a1, a2, a3;
        uint32_t aaddr = (uint32_t)__cvta_generic_to_shared(
            &As[(wm * 16 + (lane & 15)) * 72 + k0 + (lane >> 4) * 8]);
        asm volatile("ldmatrix.sync.aligned.m8n8.x4.shared.b16 {%0,%1,%2,%3}, [%4];"
                     : "=r"(a0), "=r"(a1), "=r"(a2), "=r"(a3) : "r"(aaddr));
        #pragma unroll
        for (int f = 0; f < 4; f++) {
            int n0 = wn * 32 + f * 8;
            uint32_t b0, b1r;
            uint32_t baddr = (uint32_t)__cvta_generic_to_shared(
                &Bs[(k0 + (lane & 15)) * 136 + n0]);
            asm volatile("ldmatrix.sync.aligned.m8n8.x2.trans.shared.b16 {%0,%1}, [%2];"
                         : "=r"(b0), "=r"(b1r) : "r"(baddr));
            asm volatile("mma.sync.aligned.m16n8k16.row.col.f32.f16.f16.f32 "
                         "{%0,%1,%2,%3}, {%4,%5,%6,%7}, {%8,%9}, {%0,%1,%2,%3};"
                         : "+f"(d[f][0]), "+f"(d[f][1]), "+f"(d[f][2]), "+f"(d[f][3])
                         : "r"(a0), "r"(a1), "r"(a2), "r"(a3), "r"(b0), "r"(b1r));
        }
    }

    int r = row0 + wm * 16 + (lane >> 2);
    #pragma unroll
    for (int f = 0; f < 4; f++) {
        int c = wn * 32 + f * 8 + (lane & 3) * 2;
        float2 bb = *(const float2*)&b1[c];
        *(__half2*)&g_h[(size_t)r * HID_DIM + c] =
            __floats2half2_rn(fmaxf(d[f][0] + bb.x, 0.f), fmaxf(d[f][1] + bb.y, 0.f));
        *(__half2*)&g_h[(size_t)(r + 8) * HID_DIM + c] =
            __floats2half2_rn(fmaxf(d[f][2] + bb.x, 0.f), fmaxf(d[f][3] + bb.y, 0.f));
    }
}

// ---------------- GEMM2 (HMMA): y = (h @ W2) * dinv[row], fp16 out ----------------
// block: 32 rows x 64 cols, 8 warps (2x4), warp tile 16x16, K=128 (8 k-steps)
__global__ __launch_bounds__(256) void k_gemm2(const float* __restrict__ W2) {
    __shared__ __half As[32 * 136];    // LDA=136
    __shared__ __half Bs[128 * 72];    // LDB=72
    int tid = threadIdx.x;
    int row0 = blockIdx.x * 32;

    {   // A: 32x128 halves, each thread two 16B chunks
        int row = tid >> 3, c16 = (tid & 7) * 16;
        const __half* src = &g_h[(size_t)(row0 + row) * HID_DIM + c16];
        *(uint4*)&As[row * 136 + c16]     = *(const uint4*)&src[0];
        *(uint4*)&As[row * 136 + c16 + 8] = *(const uint4*)&src[8];
    }
    // B: W2 fp32 128x64 -> fp16 shared
    #pragma unroll
    for (int i = tid; i < 128 * 64 / 4; i += 256) {
        int idx4 = i * 4;
        int k = idx4 >> 6, n = idx4 & 63;
        float4 w = *(const float4*)&W2[idx4];
        PK2 p;
        p.h[0] = __floats2half2_rn(w.x, w.y);
        p.h[1] = __floats2half2_rn(w.z, w.w);
        *(uint2*)&Bs[k * 72 + n] = p.u;
    }
    __syncthreads();

    int warp = tid >> 5, lane = tid & 31;
    int wm = warp >> 2, wn = warp & 3;
    float d[2][4] = {};

    #pragma unroll
    for (int ks = 0; ks < 8; ks++) {
        int k0 = ks * 16;
        uint32_t a0, a1, a2, a3;
        uint32_t aaddr = (uint32_t)__cvta_generic_to_shared(
            &As[(wm * 16 + (lane & 15)) * 136 + k0 + (lane >> 4) * 8]);
        asm volatile("ldmatrix.sync.aligned.m8n8.x4.shared.b16 {%0,%1,%2,%3}, [%4];"
                     : "=r"(a0), "=r"(a1), "=r"(a2), "=r"(a3) : "r"(aaddr));
        #pragma unroll
        for (int f = 0; f < 2; f++) {
            int n0 = wn * 16 + f * 8;
            uint32_t b0, b1r;
            uint32_t baddr = (uint32_t)__cvta_generic_to_shared(
                &Bs[(k0 + (lane & 15)) * 72 + n0]);
            asm volatile("ldmatrix.sync.aligned.m8n8.x2.trans.shared.b16 {%0,%1}, [%2];"
                         : "=r"(b0), "=r"(b1r) : "r"(baddr));
            asm volatile("mma.sync.aligned.m16n8k16.row.col.f32.f16.f16.f32 "
                         "{%0,%1,%2,%3}, {%4,%5,%6,%7}, {%8,%9}, {%0,%1,%2,%3};"
                         : "+f"(d[f][0]), "+f"(d[f][1]), "+f"(d[f][2]), "+f"(d[f][3])
                         : "r"(a0), "r"(a1), "r"(a2), "r"(a3), "r"(b0), "r"(b1r));
        }
    }

    int r = row0 + wm * 16 + (lane >> 2);
    float s0 = g_dinv[r], s1 = g_dinv[r + 8];
    #pragma unroll
    for (int f = 0; f < 2; f++) {
        int c = wn * 16 + f * 8 + (lane & 3) * 2;
        *(__half2*)&g_yh[(size_t)r * EMB_DIM + c] =
            __floats2half2_rn(d[f][0] * s0, d[f][1] * s0);
        *(__half2*)&g_yh[(size_t)(r + 8) * EMB_DIM + c] =
            __floats2half2_rn(d[f][2] * s1, d[f][3] * s1);
    }
}

// ---------------- gather2 + finalize: out = dinv[c]*(y[c] + sum y[r]) + b2 ----------------
__global__ __launch_bounds__(256) void k_gather2(const float* __restrict__ b2,
                                                 float* __restrict__ out) {
    int warp = threadIdx.x >> 5;
    int lane = threadIdx.x & 31;
    int node = blockIdx.x * 8 + warp;
    if (node >= N_NODES) return;
    int l = lane & 15, which = lane >> 4;

    float4 acc = make_float4(0.f, 0.f, 0.f, 0.f);
    if (which == 0) {
        uint2 u = *(const uint2*)&g_yh[(size_t)node * EMB_DIM + l * 4];
        float2 f0 = __half22float2(*(__half2*)&u.x);
        float2 f1 = __half22float2(*(__half2*)&u.y);
        acc = make_float4(f0.x, f0.y, f1.x, f1.y);
    }
    int beg = g_rowptr[node], end = g_rowptr[node + 1];
    for (int i = beg + which; i < end; i += 2) {
        uint2 u = *(const uint2*)&g_yh[(size_t)g_src[i] * EMB_DIM + l * 4];
        float2 f0 = __half22float2(*(__half2*)&u.x);
        float2 f1 = __half22float2(*(__half2*)&u.y);
        acc.x += f0.x; acc.y += f0.y; acc.z += f1.x; acc.w += f1.y;
    }
    acc.x += __shfl_xor_sync(0xffffffffu, acc.x, 16);
    acc.y += __shfl_xor_sync(0xffffffffu, acc.y, 16);
    acc.z += __shfl_xor_sync(0xffffffffu, acc.z, 16);
    acc.w += __shfl_xor_sync(0xffffffffu, acc.w, 16);

    if (which == 0) {
        float s = g_dinv[node];
        float4 bv = *(const float4*)&b2[l * 4];
        acc.x = acc.x * s + bv.x;
        acc.y = acc.y * s + bv.y;
        acc.z = acc.z * s + bv.z;
        acc.w = acc.w * s + bv.w;
        *(float4*)&out[(size_t)node * EMB_DIM + l * 4] = acc;
    }
}

extern "C" void kernel_launch(void* const* d_in, const int* in_sizes, int n_in,
                              void* d_out, int out_size) {
    const float* x  = (const float*)d_in[0];
    const int*   ei = (const int*)d_in[1];
    const float* W1 = (const float*)d_in[2];
    const float* b1 = (const float*)d_in[3];
    const float* W2 = (const float*)d_in[4];
    const float* b2 = (const float*)d_in[5];
    float* out = (float*)d_out;

    // CSR build
    k_zero_deg<<<(N_NODES + 255) / 256, 256>>>();
    k_hist<<<(N_EDGES + 255) / 256, 256>>>(ei);
    k_scan_local<<<NBLK, SCAN_B>>>();
    k_scan_final<<<(N_NODES + 255) / 256, 256>>>();
    k_fill<<<(N_EDGES + 255) / 256, 256>>>(ei);

    // layer 1: aggregate input (64-dim, fp16 payload), then HMMA GEMM
    k_xs<<<(N_NODES * (IN_DIM / 4) + 255) / 256, 256>>>(x);
    k_gather1<<<(N_NODES + 7) / 8, 256>>>();
    k_gemm1<<<N_NODES / 32, 256>>>(W1, b1);

    // layer 2: HMMA GEMM first (128->64), then aggregate + finalize
    k_gemm2<<<N_NODES / 32, 256>>>(W2);
    k_gather2<<<(N_NODES + 7) / 8, 256>>>(b2, out);
}

// round 7
// speedup vs baseline: 3.0496x; 1.0435x over previous
#include <cuda_runtime.h>
#include <cuda_fp16.h>
#include <cuda_bf16.h>
#include <cstdint>

#define N_NODES 100000
#define N_PAD   100096            // multiple of 128
#define N_EDGES 1600000
#define IN_DIM 64
#define HID_DIM 128
#define EMB_DIM 64
#define NBLK 25                   // ceil(100000/4096)

// ---- scratch (device globals; no allocation allowed) ----
__device__ __align__(16) int   g_deg[N_PAD];
__device__ __align__(16) int   g_scan[N_PAD];
__device__ int   g_bsum[NBLK];
__device__ int   g_rowptr[N_NODES + 1];
__device__ int   g_cursor[N_NODES];
__device__ int   g_src[N_EDGES];
__device__ float g_dinv[N_PAD];
__device__ __align__(16) __half g_w1h[IN_DIM * HID_DIM];
__device__ __align__(16) __half g_w2h[HID_DIM * EMB_DIM];
__device__ __align__(16) __half g_xsh [N_PAD * IN_DIM];   // x * dinv[row] (fp16)
__device__ __align__(16) __half g_aggh[N_PAD * IN_DIM];   // dinv[c] * aggregated input
__device__ __align__(16) __half g_h   [N_PAD * HID_DIM];  // hidden post-relu
__device__ __align__(16) __half g_yh  [N_PAD * EMB_DIM];  // (h @ W2) * dinv[row]

union PK2 { __half2 h[2]; uint2 u; };

// ---------------- prep: zero degrees + convert weights to fp16 ----------------
__global__ void k_prep(const float* __restrict__ W1, const float* __restrict__ W2) {
    int i = blockIdx.x * blockDim.x + threadIdx.x;
    if (i < N_NODES) g_deg[i] = 0;
    if (i < IN_DIM * HID_DIM) g_w1h[i] = __float2half(W1[i]);
    if (i < HID_DIM * EMB_DIM) g_w2h[i] = __float2half(W2[i]);
}

__global__ void k_hist(const int* __restrict__ ei) {
    int e = blockIdx.x * blockDim.x + threadIdx.x;
    if (e < N_EDGES) {
        unsigned c = (unsigned)ei[N_EDGES + e];
        if (c < N_NODES) atomicAdd(&g_deg[c], 1);
    }
}

// block scans 4096 elements (4/thread), warp-shfl based (2 barriers)
__global__ __launch_bounds__(1024) void k_scan_local() {
    __shared__ int ws[32];
    int tid = threadIdx.x, lane = tid & 31, wid = tid >> 5;
    int base = blockIdx.x * 4096 + tid * 4;
    int4 v = {0, 0, 0, 0};
    if (base + 3 < N_NODES) v = *(const int4*)&g_deg[base];
    else {
        if (base + 0 < N_NODES) v.x = g_deg[base + 0];
        if (base + 1 < N_NODES) v.y = g_deg[base + 1];
        if (base + 2 < N_NODES) v.z = g_deg[base + 2];
        if (base + 3 < N_NODES) v.w = g_deg[base + 3];
    }
    int p0 = v.x, p1 = p0 + v.y, p2 = p1 + v.z, p3 = p2 + v.w;
    int ws_incl = p3;
    #pragma unroll
    for (int off = 1; off < 32; off <<= 1) {
        int t = __shfl_up_sync(0xffffffffu, ws_incl, off);
        if (lane >= off) ws_incl += t;
    }
    if (lane == 31) ws[wid] = ws_incl;
    __syncthreads();
    if (wid == 0) {
        int t = ws[lane];
        #pragma unroll
        for (int off = 1; off < 32; off <<= 1) {
            int u = __shfl_up_sync(0xffffffffu, t, off);
            if (lane >= off) t += u;
        }
        ws[lane] = t;
    }
    __syncthreads();
    int woff = (wid == 0) ? 0 : ws[wid - 1];
    int excl = woff + ws_incl - p3;
    if (base + 3 < N_NODES) {
        int4 o = {excl + p0, excl + p1, excl + p2, excl + p3};
        *(int4*)&g_scan[base] = o;
    } else {
        if (base + 0 < N_NODES) g_scan[base + 0] = excl + p0;
        if (base + 1 < N_NODES) g_scan[base + 1] = excl + p1;
        if (base + 2 < N_NODES) g_scan[base + 2] = excl + p2;
        if (base + 3 < N_NODES) g_scan[base + 3] = excl + p3;
    }
    if (tid == 1023) g_bsum[blockIdx.x] = ws[31];
}

__global__ __launch_bounds__(256) void k_scan_final() {
    __shared__ int s[32];
    int tid = threadIdx.x;
    if (tid < 32) {
        int v = (tid < NBLK) ? g_bsum[tid] : 0;
        #pragma unroll
        for (int off = 1; off < 32; off <<= 1) {
            int t = __shfl_up_sync(0xffffffffu, v, off);
            if (tid >= off) v += t;
        }
        s[tid] = v;
    }
    __syncthreads();
    int i = blockIdx.x * 256 + tid;
    if (i >= N_NODES) return;
    int blk = i >> 12;
    int boff = blk ? s[blk - 1] : 0;
    int deg = g_deg[i];
    int incl = g_scan[i] + boff;
    int excl = incl - deg;
    g_rowptr[i] = excl;
    g_cursor[i] = excl;
    g_dinv[i] = rsqrtf((float)deg + 1.0f);
    if (i == N_NODES - 1) g_rowptr[N_NODES] = incl;
}

__global__ void k_fill(const int* __restrict__ ei) {
    int e = blockIdx.x * blockDim.x + threadIdx.x;
    if (e >= N_EDGES) return;
    unsigned r = (unsigned)ei[e];
    unsigned c = (unsigned)ei[N_EDGES + e];
    if (r < N_NODES && c < N_NODES) {
        int pos = atomicAdd(&g_cursor[c], 1);
        g_src[pos] = (int)r;
    }
}

// ---------------- xs = x * dinv[row]  (fp32 -> fp16) ----------------
__global__ void k_xs(const float* __restrict__ x) {
    int i = blockIdx.x * blockDim.x + threadIdx.x;   // float4 index
    if (i >= N_NODES * (IN_DIM / 4)) return;
    int node = i >> 4;
    float s = g_dinv[node];
    float4 v = *(const float4*)&x[i * 4];
    PK2 p;
    p.h[0] = __floats2half2_rn(v.x * s, v.y * s);
    p.h[1] = __floats2half2_rn(v.z * s, v.w * s);
    *(uint2*)&g_xsh[i * 4] = p.u;
}

// ---------------- gather1: aggh[c] = dinv[c]*(xs[c] + sum xs[r]) ----------------
// one warp per node; prefetch up to 32 src indices, full warp loads one 128B row/iter
__global__ __launch_bounds__(256) void k_gather1() {
    int warp = threadIdx.x >> 5;
    int lane = threadIdx.x & 31;
    int node = blockIdx.x * 8 + warp;
    if (node >= N_NODES) return;
    const uint32_t* tab = (const uint32_t*)g_xsh;   // 32 uints per row

    float2 acc = __half22float2(*(const __half2*)&tab[node * 32 + lane]);
    int beg = g_rowptr[node], end = g_rowptr[node + 1];
    int cnt = end - beg;
    int my = (lane < cnt) ? g_src[beg + lane] : 0;
    int lim = cnt < 32 ? cnt : 32;
    for (int j = 0; j < lim; j++) {
        int r = __shfl_sync(0xffffffffu, my, j);
        float2 v = __half22float2(*(const __half2*)&tab[r * 32 + lane]);
        acc.x += v.x; acc.y += v.y;
    }
    for (int i = beg + 32; i < end; i++) {
        int r = g_src[i];
        float2 v = __half22float2(*(const __half2*)&tab[r * 32 + lane]);
        acc.x += v.x; acc.y += v.y;
    }
    float s = g_dinv[node];
    ((__half2*)g_aggh)[node * 32 + lane] = __floats2half2_rn(acc.x * s, acc.y * s);
}

// ---------------- GEMM1 (HMMA): h = relu(aggh @ W1 + b1), fp16 out ----------------
// 128x128 tile, K=64; 8 warps (4M x 2N), warp tile 32x64
__global__ __launch_bounds__(256) void k_gemm1(const float* __restrict__ b1) {
    __shared__ __half As[128 * 72];    // 18432 B
    __shared__ __half Bs[64 * 136];    // 17408 B
    int tid = threadIdx.x;
    int row0 = blockIdx.x * 128;

    #pragma unroll
    for (int i = tid; i < 1024; i += 256) {          // A: 128x64, uint4 chunks
        int row = i >> 3, c = (i & 7) * 8;
        *(uint4*)&As[row * 72 + c] = *(const uint4*)&g_aggh[(size_t)(row0 + row) * IN_DIM + c];
    }
    #pragma unroll
    for (int i = tid; i < 1024; i += 256) {          // B: 64x128 fp16
        int k = i >> 4, n = (i & 15) * 8;
        *(uint4*)&Bs[k * 136 + n] = *(const uint4*)&g_w1h[k * 128 + n];
    }
    __syncthreads();

    int warp = tid >> 5, lane = tid & 31;
    int wm = warp >> 1, wn = warp & 1;               // 4 x 2
    float d[2][8][4] = {};

    #pragma unroll
    for (int ks = 0; ks < 4; ks++) {
        int k0 = ks * 16;
        uint32_t a[2][4];
        #pragma unroll
        for (int mf = 0; mf < 2; mf++) {
            uint32_t aaddr = (uint32_t)__cvta_generic_to_shared(
                &As[(wm * 32 + mf * 16 + (lane & 15)) * 72 + k0 + (lane >> 4) * 8]);
            asm volatile("ldmatrix.sync.aligned.m8n8.x4.shared.b16 {%0,%1,%2,%3}, [%4];"
                         : "=r"(a[mf][0]), "=r"(a[mf][1]), "=r"(a[mf][2]), "=r"(a[mf][3])
                         : "r"(aaddr));
        }
        #pragma unroll
        for (int nfl = 0; nfl < 4; nfl++) {
            int n0 = wn * 64 + nfl * 16;
            uint32_t b[4];
            uint32_t baddr = (uint32_t)__cvta_generic_to_shared(
                &Bs[(k0 + (lane & 15)) * 136 + n0 + (lane >> 4) * 8]);
            asm volatile("ldmatrix.sync.aligned.m8n8.x4.trans.shared.b16 {%0,%1,%2,%3}, [%4];"
                         : "=r"(b[0]), "=r"(b[1]), "=r"(b[2]), "=r"(b[3]) : "r"(baddr));
            #pragma unroll
            for (int mf = 0; mf < 2; mf++) {
                #pragma unroll
                for (int p = 0; p < 2; p++) {
                    float* dd = d[mf][nfl * 2 + p];
                    asm volatile("mma.sync.aligned.m16n8k16.row.col.f32.f16.f16.f32 "
                                 "{%0,%1,%2,%3}, {%4,%5,%6,%7}, {%8,%9}, {%0,%1,%2,%3};"
                                 : "+f"(dd[0]), "+f"(dd[1]), "+f"(dd[2]), "+f"(dd[3])
                                 : "r"(a[mf][0]), "r"(a[mf][1]), "r"(a[mf][2]), "r"(a[mf][3]),
                                   "r"(b[p * 2]), "r"(b[p * 2 + 1]));
                }
            }
        }
    }

    #pragma unroll
    for (int mf = 0; mf < 2; mf++) {
        int r = row0 + wm * 32 + mf * 16 + (lane >> 2);
        #pragma unroll
        for (int nf = 0; nf < 8; nf++) {
            int c = wn * 64 + nf * 8 + (lane & 3) * 2;
            float2 bb = *(const float2*)&b1[c];
            float* dd = d[mf][nf];
            *(__half2*)&g_h[(size_t)r * HID_DIM + c] =
                __floats2half2_rn(fmaxf(dd[0] + bb.x, 0.f), fmaxf(dd[1] + bb.y, 0.f));
            *(__half2*)&g_h[(size_t)(r + 8) * HID_DIM + c] =
                __floats2half2_rn(fmaxf(dd[2] + bb.x, 0.f), fmaxf(dd[3] + bb.y, 0.f));
        }
    }
}

// ---------------- GEMM2 (HMMA): y = (h @ W2) * dinv[row], fp16 out ----------------
// 64x64 tile, K=128; 8 warps (4M x 2N), warp tile 16x32
__global__ __launch_bounds__(256) void k_gemm2() {
    __shared__ __half As[64 * 136];    // 17408 B
    __shared__ __half Bs[128 * 72];    // 18432 B
    int tid = threadIdx.x;
    int row0 = blockIdx.x * 64;

    #pragma unroll
    for (int i = tid; i < 1024; i += 256) {          // A: 64x128
        int row = i >> 4, c = (i & 15) * 8;
        *(uint4*)&As[row * 136 + c] = *(const uint4*)&g_h[(size_t)(row0 + row) * HID_DIM + c];
    }
    #pragma unroll
    for (int i = tid; i < 1024; i += 256) {          // B: 128x64 fp16
        int k = i >> 3, n = (i & 7) * 8;
        *(uint4*)&Bs[k * 72 + n] = *(const uint4*)&g_w2h[k * 64 + n];
    }
    __syncthreads();

    int warp = tid >> 5, lane = tid & 31;
    int wm = warp >> 1, wn = warp & 1;               // 4 x 2
    float d[4][4] = {};

    #pragma unroll
    for (int ks = 0; ks < 8; ks++) {
        int k0 = ks * 16;
        uint32_t a[4];
        uint32_t aaddr = (uint32_t)__cvta_generic_to_shared(
            &As[(wm * 16 + (lane & 15)) * 136 + k0 + (lane >> 4) * 8]);
        asm volatile("ldmatrix.sync.aligned.m8n8.x4.shared.b16 {%0,%1,%2,%3}, [%4];"
                     : "=r"(a[0]), "=r"(a[1]), "=r"(a[2]), "=r"(a[3]) : "r"(aaddr));
        #pragma unroll
        for (int nfl = 0; nfl < 2; nfl++) {
            int n0 = wn * 32 + nfl * 16;
            uint32_t b[4];
            uint32_t baddr = (uint32_t)__cvta_generic_to_shared(
                &Bs[(k0 + (lane & 15)) * 72 + n0 + (lane >> 4) * 8]);
            asm volatile("ldmatrix.sync.aligned.m8n8.x4.trans.shared.b16 {%0,%1,%2,%3}, [%4];"
                         : "=r"(b[0]), "=r"(b[1]), "=r"(b[2]), "=r"(b[3]) : "r"(baddr));
            #pragma unroll
            for (int p = 0; p < 2; p++) {
                float* dd = d[nfl * 2 + p];
                asm volatile("mma.sync.aligned.m16n8k16.row.col.f32.f16.f16.f32 "
                             "{%0,%1,%2,%3}, {%4,%5,%6,%7}, {%8,%9}, {%0,%1,%2,%3};"
                             : "+f"(dd[0]), "+f"(dd[1]), "+f"(dd[2]), "+f"(dd[3])
                             : "r"(a[0]), "r"(a[1]), "r"(a[2]), "r"(a[3]),
                               "r"(b[p * 2]), "r"(b[p * 2 + 1]));
            }
        }
    }

    int r = row0 + wm * 16 + (lane >> 2);
    float s0 = g_dinv[r], s1 = g_dinv[r + 8];
    #pragma unroll
    for (int nf = 0; nf < 4; nf++) {
        int c = wn * 32 + nf * 8 + (lane & 3) * 2;
        float* dd = d[nf];
        *(__half2*)&g_yh[(size_t)r * EMB_DIM + c] =
            __floats2half2_rn(dd[0] * s0, dd[1] * s0);
        *(__half2*)&g_yh[(size_t)(r + 8) * EMB_DIM + c] =
            __floats2half2_rn(dd[2] * s1, dd[3] * s1);
    }
}

// ---------------- gather2 + finalize: out = dinv[c]*(y[c] + sum y[r]) + b2 ----------------
__global__ __launch_bounds__(256) void k_gather2(const float* __restrict__ b2,
                                                 float* __restrict__ out) {
    int warp = threadIdx.x >> 5;
    int lane = threadIdx.x & 31;
    int node = blockIdx.x * 8 + warp;
    if (node >= N_NODES) return;
    const uint32_t* tab = (const uint32_t*)g_yh;

    float2 acc = __half22float2(*(const __half2*)&tab[node * 32 + lane]);
    int beg = g_rowptr[node], end = g_rowptr[node + 1];
    int cnt = end - beg;
    int my = (lane < cnt) ? g_src[beg + lane] : 0;
    int lim = cnt < 32 ? cnt : 32;
    for (int j = 0; j < lim; j++) {
        int r = __shfl_sync(0xffffffffu, my, j);
        float2 v = __half22float2(*(const __half2*)&tab[r * 32 + lane]);
        acc.x += v.x; acc.y += v.y;
    }
    for (int i = beg + 32; i < end; i++) {
        int r = g_src[i];
        float2 v = __half22float2(*(const __half2*)&tab[r * 32 + lane]);
        acc.x += v.x; acc.y += v.y;
    }
    float s = g_dinv[node];
    float2 bv = *(const float2*)&b2[lane * 2];
    float2 o = {acc.x * s + bv.x, acc.y * s + bv.y};
    *(float2*)&out[(size_t)node * EMB_DIM + lane * 2] = o;
}

extern "C" void kernel_launch(void* const* d_in, const int* in_sizes, int n_in,
                              void* d_out, int out_size) {
    const float* x  = (const float*)d_in[0];
    const int*   ei = (const int*)d_in[1];
    const float* W1 = (const float*)d_in[2];
    const float* b1 = (const float*)d_in[3];
    const float* W2 = (const float*)d_in[4];
    const float* b2 = (const float*)d_in[5];
    float* out = (float*)d_out;

    k_prep<<<(N_NODES + 255) / 256, 256>>>(W1, W2);
    k_hist<<<(N_EDGES + 255) / 256, 256>>>(ei);
    k_scan_local<<<NBLK, 1024>>>();
    k_scan_final<<<(N_NODES + 255) / 256, 256>>>();
    k_fill<<<(N_EDGES + 255) / 256, 256>>>(ei);

    k_xs<<<(N_NODES * (IN_DIM / 4) + 255) / 256, 256>>>(x);
    k_gather1<<<(N_NODES + 7) / 8, 256>>>();
    k_gemm1<<<N_PAD / 128, 256>>>(b1);

    k_gemm2<<<N_PAD / 64, 256>>>();
    k_gather2<<<(N_NODES + 7) / 8, 256>>>(b2, out);
}